// round 9
// baseline (speedup 1.0000x reference)
#include <cuda_runtime.h>
#include <cuda_fp16.h>
#include <cstdint>

#define BB   64
#define TT   128
#define VV   10000
#define EE   300
#define HH   1024
#define G4   4096
#define TM1  127
#define MROWS 8128
#define KE   320        // padded E
#define NPADV 10112     // padded V (79*128)
#define NCTA 96         // persistent grid: 96 CTAs x 512 thr (residency-guaranteed)
#define NTHRP (NCTA * 512)

typedef __half fp16;

// ---------------- scratch (device globals) -----------------------------------
__device__ __align__(16) fp16  g_emb [MROWS * KE];
__device__ __align__(16) float g_pre0[(size_t)MROWS * G4];
__device__ __align__(16) float g_gp0 [2 * BB * G4];
__device__ __align__(16) float g_gp1 [4 * BB * G4];
__device__ __align__(16) float g_c0  [BB * HH];
__device__ __align__(16) float g_c1  [BB * HH];
__device__ __align__(16) fp16  g_h0H [BB * HH];
__device__ __align__(16) fp16  g_h1H [BB * HH];
__device__ __align__(16) fp16  g_H1  [(size_t)MROWS * HH];
__device__ __align__(16) fp16  g_wih0T[G4 * KE];
__device__ __align__(16) fp16  g_whh0T[G4 * HH];
__device__ __align__(16) fp16  g_w1T [G4 * 2048];
__device__ __align__(16) fp16  g_woutT[(size_t)NPADV * HH];
__device__ __align__(16) float g_rowsum[MROWS];
__device__ float g_lossb[BB];
__device__ unsigned g_bar_cnt = 0;      // self-resetting (atomicInc wrap)
__device__ unsigned g_bar_sense = 0;    // returns to 0 (even barrier count)

// ---------------- fast math (FMA-only exp) -----------------------------------
__device__ __forceinline__ float fexp(float x) {
    x = fminf(x, 88.0f);
    if (x < -87.0f) return 0.0f;
    float t = fmaf(x, 1.4426950408889634f, 12582912.0f);
    float n = t - 12582912.0f;
    int   e = __float_as_int(t) - 0x4B400000;
    float r = fmaf(n, -0.693359375f, x);
    r = fmaf(n, 2.1219444e-4f, r);
    float p = fmaf(8.3333333e-3f, r, 4.1666668e-2f);
    p = fmaf(p, r, 1.6666667e-1f);
    p = fmaf(p, r, 0.5f);
    p = fmaf(p, r, 1.0f);
    p = fmaf(p, r, 1.0f);
    return __int_as_float(__float_as_int(p) + (e << 23));
}
__device__ __forceinline__ float sigf(float x)  { return 1.0f / (1.0f + fexp(-x)); }
__device__ __forceinline__ float tanhf_(float x){ return fmaf(2.0f, sigf(2.0f * x), -1.0f); }

// ---------------- ptx helpers -------------------------------------------------
__device__ __forceinline__ uint32_t smem_u32(const void* p) {
    uint32_t a;
    asm("{ .reg .u64 t; cvta.to.shared.u64 t, %1; cvt.u32.u64 %0, t; }" : "=r"(a) : "l"(p));
    return a;
}
__device__ __forceinline__ void cpa16(uint32_t dst, const void* src, int valid) {
    asm volatile("cp.async.cg.shared.global [%0], [%1], 16, %2;"
                 :: "r"(dst), "l"(src), "r"(valid) : "memory");
}
#define CP_COMMIT()  asm volatile("cp.async.commit_group;" ::: "memory")
#define CP_WAIT(n)   asm volatile("cp.async.wait_group %0;" :: "n"(n) : "memory")

__device__ __forceinline__ void ldm4(uint32_t* r, uint32_t addr) {
    asm volatile("ldmatrix.sync.aligned.m8n8.x4.shared.b16 {%0,%1,%2,%3}, [%4];"
                 : "=r"(r[0]), "=r"(r[1]), "=r"(r[2]), "=r"(r[3]) : "r"(addr));
}
__device__ __forceinline__ void mma16816(float* d, const uint32_t* a, const uint32_t* b) {
    asm volatile(
        "mma.sync.aligned.m16n8k16.row.col.f32.f16.f16.f32 "
        "{%0,%1,%2,%3}, {%4,%5,%6,%7}, {%8,%9}, {%0,%1,%2,%3};"
        : "+f"(d[0]), "+f"(d[1]), "+f"(d[2]), "+f"(d[3])
        : "r"(a[0]), "r"(a[1]), "r"(a[2]), "r"(a[3]), "r"(b[0]), "r"(b[1]));
}
#define SW128(x) ((x) ^ (((x) >> 3) & 0x70))

// ---------------- grid barrier (sense-reversing, self-restoring) --------------
__device__ __forceinline__ void gridbar(unsigned& lsense) {
    __syncthreads();
    lsense ^= 1u;
    if (threadIdx.x == 0) {
        __threadfence();
        unsigned old = atomicInc(&g_bar_cnt, NCTA - 1);
        if (old == NCTA - 1) {
            atomicExch(&g_bar_sense, lsense);
        } else {
            while (*((volatile unsigned*)&g_bar_sense) != lsense) __nanosleep(40);
        }
    }
    __syncthreads();
}

// ---------------- init / gather / prep ---------------------------------------
__global__ void zero_state() {
    int idx = blockIdx.x * 256 + threadIdx.x;        // 65536 threads
    fp16 z = __float2half_rn(0.0f);
    g_h0H[idx] = z; g_h1H[idx] = z;
    g_c0[idx] = 0.f; g_c1[idx] = 0.f;
    if (idx < MROWS) g_rowsum[idx] = 0.f;
    if (idx < BB) g_lossb[idx] = 0.f;
}

__global__ void gather_emb(const int* __restrict__ sent, const float* __restrict__ wordvec) {
    int idx = blockIdx.x * 256 + threadIdx.x;
    if (idx >= MROWS * KE) return;
    int r = idx / KE, k = idx - r * KE;
    int t = r >> 6, b = r & 63;
    float v = 0.f;
    if (k < EE) { int w = sent[b * TT + t]; v = wordvec[(size_t)w * EE + k]; }
    g_emb[idx] = __float2half_rn(v);
}

__global__ void prep_T(const float* __restrict__ W, int Ksrc, int Nsrc,
                       fp16* __restrict__ O,
                       int Kpad, int koff, int Kspan, int Npad) {
    __shared__ float ts[32][33];
    int k0 = blockIdx.x * 32, n0 = blockIdx.y * 32;
    int tx = threadIdx.x, ty = threadIdx.y;
#pragma unroll
    for (int i = 0; i < 4; i++) {
        int k = k0 + ty + i * 8, n = n0 + tx;
        float v = (k < Ksrc && n < Nsrc) ? W[(size_t)k * Nsrc + n] : 0.f;
        ts[ty + i * 8][tx] = v;
    }
    __syncthreads();
#pragma unroll
    for (int i = 0; i < 4; i++) {
        int n = n0 + ty + i * 8, k = k0 + tx;
        if (n < Npad && k < Kspan)
            O[(size_t)n * Kpad + koff + k] = __float2half_rn(ts[tx][ty + i * 8]);
    }
}

// ---------------- big GEMM (128x128 tile, 3-stage, single-pass fp16) ----------
#define BSTAGE 32768
__device__ __forceinline__ void ldstage_b(
    uint32_t st, int tid, int m0, int n0, int k0,
    const fp16* A, int lda, const fp16* B, int ldb, int Mreal)
{
#pragma unroll
    for (int e = tid; e < 1024; e += 256) {
        int r = e >> 3, c = e & 7;
        uint32_t sw = SW128((uint32_t)(r * 128 + c * 16));
        int gr = m0 + r;
        int ok = 16;
        if (gr >= Mreal) { ok = 0; gr = 0; }
        cpa16(st + sw, A + (size_t)gr * lda + k0 + c * 8, ok);
    }
#pragma unroll
    for (int e = tid; e < 1024; e += 256) {
        int r = e >> 3, c = e & 7;
        uint32_t sw = SW128((uint32_t)(r * 128 + c * 16));
        cpa16(st + 16384 + sw, B + (size_t)(n0 + r) * ldb + k0 + c * 8, 16);
    }
}

__global__ __launch_bounds__(256, 1) void gemm_big(
    const fp16* __restrict__ A, int lda,
    const fp16* __restrict__ B, int ldb,
    int K, int Mreal, int Nreal,
    const float* __restrict__ bias, float* __restrict__ C, int ldc,
    float* __restrict__ rowsum, int mode)
{
    extern __shared__ char smem[];
    int tid = threadIdx.x, lane = tid & 31, wid = tid >> 5;
    int wm = wid & 1, wn = wid >> 1;
    int n0 = blockIdx.x * 128, m0 = blockIdx.y * 128;
    int nch = K >> 6;

    uint32_t sb = smem_u32(smem);
    float acc[4][4][4];
#pragma unroll
    for (int i = 0; i < 4; i++)
#pragma unroll
        for (int j = 0; j < 4; j++)
#pragma unroll
            for (int v = 0; v < 4; v++) acc[i][j][v] = 0.f;

    ldstage_b(sb, tid, m0, n0, 0, A, lda, B, ldb, Mreal);
    CP_COMMIT();
    if (nch > 1) ldstage_b(sb + BSTAGE, tid, m0, n0, 64, A, lda, B, ldb, Mreal);
    CP_COMMIT();

    for (int ic = 0; ic < nch; ic++) {
        if (ic + 2 < nch)
            ldstage_b(sb + (uint32_t)((ic + 2) % 3) * BSTAGE, tid, m0, n0,
                      (ic + 2) * 64, A, lda, B, ldb, Mreal);
        CP_COMMIT();
        CP_WAIT(2);
        __syncthreads();
        uint32_t st = sb + (uint32_t)(ic % 3) * BSTAGE;
#pragma unroll
        for (int q = 0; q < 4; q++) {
            uint32_t ah[4][4];
            int arow = wm * 64 + (lane & 15);
            int ach  = q * 32 + ((lane >> 4) << 4);
#pragma unroll
            for (int mt = 0; mt < 4; mt++)
                ldm4(ah[mt], st + SW128((uint32_t)((arow + mt * 16) * 128 + ach)));
            uint32_t bh[2][4];
            int brow = wn * 32 + (lane & 7) + (((lane >> 4) & 1) << 3);
            int bch  = q * 32 + (((lane >> 3) & 1) << 4);
#pragma unroll
            for (int p = 0; p < 2; p++)
                ldm4(bh[p], st + 16384 + SW128((uint32_t)((brow + p * 16) * 128 + bch)));
#pragma unroll
            for (int mt = 0; mt < 4; mt++)
#pragma unroll
                for (int p = 0; p < 2; p++)
#pragma unroll
                    for (int h = 0; h < 2; h++)
                        mma16816(acc[mt][p * 2 + h], ah[mt], &bh[p][h * 2]);
        }
        __syncthreads();
    }

    int rbase = m0 + wm * 64 + (lane >> 2);
    int cbase = n0 + wn * 32 + (lane & 3) * 2;
    float rs[8];
#pragma unroll
    for (int i = 0; i < 8; i++) rs[i] = 0.f;
#pragma unroll
    for (int mt = 0; mt < 4; mt++)
#pragma unroll
        for (int nt = 0; nt < 4; nt++) {
            int col = cbase + nt * 8;
            int r0 = rbase + mt * 16;
            if (col < Nreal) {
                float ba = bias[col], bb = bias[col + 1];
#pragma unroll
                for (int rp = 0; rp < 2; rp++) {
                    int row = r0 + rp * 8;
                    if (row < Mreal) {
                        float v0 = acc[mt][nt][rp * 2]     + ba;
                        float v1 = acc[mt][nt][rp * 2 + 1] + bb;
                        C[(size_t)row * ldc + col]     = v0;
                        C[(size_t)row * ldc + col + 1] = v1;
                        if (mode == 2) {
                            float s = fexp(v0);
                            if (col + 1 < Nreal) s += fexp(v1);
                            rs[mt * 2 + rp] += s;
                        }
                    }
                }
            }
        }
    if (mode == 2) {
#pragma unroll
        for (int i = 0; i < 8; i++) {
            rs[i] += __shfl_xor_sync(0xffffffffu, rs[i], 1);
            rs[i] += __shfl_xor_sync(0xffffffffu, rs[i], 2);
        }
        if ((lane & 3) == 0) {
#pragma unroll
            for (int mt = 0; mt < 4; mt++)
#pragma unroll
                for (int rp = 0; rp < 2; rp++) {
                    int row = rbase + mt * 16 + rp * 8;
                    if (row < Mreal) atomicAdd(&rowsum[row], rs[mt * 2 + rp]);
                }
        }
    }
}

// ---------------- persistent recurrence (96 CTA x 512 thr, 2 units/CTA) -------
#define RSTAGE 24576
#define WGSM   73728   // per-warpgroup smem partition (3 stages)
__device__ __forceinline__ void ldstage_r(
    uint32_t st, int wtid, int n0, int kA, int kB,
    const fp16* Ah, const fp16* B, int ldb)
{
#pragma unroll
    for (int e = wtid; e < 512; e += 256) {
        int r = e >> 3, c = e & 7;
        uint32_t sw = SW128((uint32_t)(r * 128 + c * 16));
        cpa16(st + sw, Ah + (size_t)r * 1024 + kA + c * 8, 16);
    }
#pragma unroll
    for (int e = wtid; e < 1024; e += 256) {
        int r = e >> 3, c = e & 7;
        uint32_t sw = SW128((uint32_t)(r * 128 + c * 16));
        cpa16(st + 8192 + sw, B + (size_t)(n0 + r) * ldb + kB + c * 8, 16);
    }
}

// one 64x128x512 K-slice GEMM unit (z = 0..5); __syncthreads spans both
// warpgroups — safe because both run identical 8-chunk structure.
__device__ __forceinline__ void gemm_phase(uint32_t sb, int wtid, int lane, int wn,
                                           int ntile, int z) {
    const fp16 *Ah, *Bp;
    float* gpo;
    int kA, kB, ldb, zi;
    int n0 = ntile * 128;
    if (z < 2) {
        Ah = g_h0H; kA = z * 512;
        Bp = g_whh0T; ldb = 1024; kB = z * 512;
        gpo = g_gp0; zi = z;
    } else {
        int zz = z - 2;
        if (zz < 2) { Ah = g_h0H; kA = zz * 512; }
        else        { Ah = g_h1H; kA = (zz - 2) * 512; }
        Bp = g_w1T; ldb = 2048; kB = zz * 512;
        gpo = g_gp1; zi = zz;
    }

    float acc[4][2][4];
#pragma unroll
    for (int i = 0; i < 4; i++)
#pragma unroll
        for (int j = 0; j < 2; j++)
#pragma unroll
            for (int v = 0; v < 4; v++) acc[i][j][v] = 0.f;

    ldstage_r(sb, wtid, n0, kA, kB, Ah, Bp, ldb);
    CP_COMMIT();
    ldstage_r(sb + RSTAGE, wtid, n0, kA + 64, kB + 64, Ah, Bp, ldb);
    CP_COMMIT();

    for (int ic = 0; ic < 8; ic++) {
        if (ic + 2 < 8)
            ldstage_r(sb + (uint32_t)((ic + 2) % 3) * RSTAGE, wtid, n0,
                      kA + (ic + 2) * 64, kB + (ic + 2) * 64, Ah, Bp, ldb);
        CP_COMMIT();
        CP_WAIT(2);
        __syncthreads();
        uint32_t st = sb + (uint32_t)(ic % 3) * RSTAGE;
#pragma unroll
        for (int q = 0; q < 4; q++) {
            uint32_t ah[4][4];
            int arow = lane & 15;
            int ach  = q * 32 + ((lane >> 4) << 4);
#pragma unroll
            for (int mt = 0; mt < 4; mt++)
                ldm4(ah[mt], st + SW128((uint32_t)((arow + mt * 16) * 128 + ach)));
            uint32_t bh[4];
            int brow = wn * 16 + (lane & 7) + (((lane >> 4) & 1) << 3);
            int bch  = q * 32 + (((lane >> 3) & 1) << 4);
            ldm4(bh, st + 8192 + SW128((uint32_t)(brow * 128 + bch)));
#pragma unroll
            for (int mt = 0; mt < 4; mt++)
#pragma unroll
                for (int h = 0; h < 2; h++)
                    mma16816(acc[mt][h], ah[mt], &bh[h * 2]);
        }
        __syncthreads();
    }

    int rbase = zi * 64 + (lane >> 2);
    int cbase = n0 + wn * 16 + (lane & 3) * 2;
#pragma unroll
    for (int mt = 0; mt < 4; mt++)
#pragma unroll
        for (int nt = 0; nt < 2; nt++) {
            int col = cbase + nt * 8;
            int r0 = rbase + mt * 16;
            gpo[(size_t)r0 * G4 + col]           = acc[mt][nt][0];
            gpo[(size_t)r0 * G4 + col + 1]       = acc[mt][nt][1];
            gpo[(size_t)(r0 + 8) * G4 + col]     = acc[mt][nt][2];
            gpo[(size_t)(r0 + 8) * G4 + col + 1] = acc[mt][nt][3];
        }
}

// LSTM update phase: upd0(t+1) (nz0 gp0 partials; -1 = skip) || upd1(t) (do1)
__device__ __forceinline__ void upd_phase(int t, int nz0, int do1,
                                          const float* __restrict__ b1, int gthread) {
    for (int gidx = gthread; gidx < 131072; gidx += NTHRP) {
        if (gidx < 65536) {
            if (nz0 < 0) continue;
            int b = gidx >> 10, h = gidx & 1023;
            const float* pre = g_pre0 + ((size_t)((t + 1) * 64 + b)) * G4;
            float gi = pre[h], gf = pre[1024 + h], gg = pre[2048 + h], go = pre[3072 + h];
            for (int z = 0; z < nz0; z++) {
                const float* gpp = g_gp0 + ((size_t)(z * 64 + b)) * G4;
                gi += __ldcg(&gpp[h]);        gf += __ldcg(&gpp[1024 + h]);
                gg += __ldcg(&gpp[2048 + h]); go += __ldcg(&gpp[3072 + h]);
            }
            float c = sigf(gf) * g_c0[gidx] + sigf(gi) * tanhf_(gg);
            float hn = sigf(go) * tanhf_(c);
            g_c0[gidx] = c;
            g_h0H[gidx] = __float2half_rn(hn);
        } else {
            if (!do1) continue;
            int idx = gidx - 65536;
            int b = idx >> 10, h = idx & 1023;
            float gi = b1[h], gf = b1[1024 + h], gg = b1[2048 + h], go = b1[3072 + h];
#pragma unroll
            for (int z = 0; z < 4; z++) {
                const float* gpp = g_gp1 + ((size_t)(z * 64 + b)) * G4;
                gi += __ldcg(&gpp[h]);        gf += __ldcg(&gpp[1024 + h]);
                gg += __ldcg(&gpp[2048 + h]); go += __ldcg(&gpp[3072 + h]);
            }
            float c = sigf(gf) * g_c1[idx] + sigf(gi) * tanhf_(gg);
            float hn = sigf(go) * tanhf_(c);
            g_c1[idx] = c;
            fp16 hi = __float2half_rn(hn);
            g_h1H[idx] = hi;
            g_H1[((size_t)b * TM1 + t) * HH + h] = hi;
        }
    }
}

__global__ __launch_bounds__(512, 1) void rec_persist(const float* __restrict__ b1) {
    extern __shared__ char smem[];
    int tid = threadIdx.x;
    int wg = tid >> 8, wtid = tid & 255;
    int lane = tid & 31, wn = wtid >> 5;
    int cta = blockIdx.x;                 // 0..95
    int unit = cta * 2 + wg;              // 0..191
    int ntile = unit & 31, z = unit >> 5;
    int gthread = cta * 512 + tid;
    uint32_t sb = smem_u32(smem) + (uint32_t)wg * WGSM;
    unsigned lsense = 0;

    // prologue: h0(0) from pre0[0] only
    upd_phase(-1, 0, 0, b1, gthread);
    gridbar(lsense);                                       // 1

    for (int s = 0; s < TM1; s++) {
        bool last = (s == TM1 - 1);
        // last-step skip is uniform per CTA: units 0..63 <=> ctas 0..31
        if (!(last && cta < 32))
            gemm_phase(sb, wtid, lane, wn, ntile, z);
        gridbar(lsense);                                   // +127
        if (!last) {
            upd_phase(s, 2, 1, b1, gthread);
            gridbar(lsense);                               // +126
        } else {
            upd_phase(s, -1, 1, b1, gthread);
        }
    }
    // total barriers = 254 (even -> g_bar_sense restored to 0)
}

// ---------------- loss --------------------------------------------------------
__global__ void loss_pick(const float* __restrict__ temp, const int* __restrict__ sent) {
    int idx = blockIdx.x * 256 + threadIdx.x;
    if (idx >= MROWS) return;
    int b = idx / TM1, t = idx - b * TM1;
    int gt = sent[b * TT + t + 1];
    if (gt != 0) {
        float lp = temp[(size_t)idx * VV + gt] - logf(g_rowsum[idx]);
        atomicAdd(&g_lossb[b], lp);
    }
}

__global__ void loss_final(const int* __restrict__ length, float* __restrict__ out) {
    int tid = threadIdx.x;  // 64 threads
    float v = -g_lossb[tid] / (float)length[tid];
#pragma unroll
    for (int o = 16; o; o >>= 1) v += __shfl_xor_sync(0xffffffffu, v, o);
    __shared__ float r2[2];
    if ((tid & 31) == 0) r2[tid >> 5] = v;
    __syncthreads();
    if (tid == 0) out[0] = r2[0] + r2[1];
}

// ---------------- launch ------------------------------------------------------
#define SMEMB 98304    // gemm_big: 3 * 32768
#define SMEMP 147456   // rec_persist: 2 warpgroups * 3 * 24576

extern "C" void kernel_launch(void* const* d_in, const int* in_sizes, int n_in,
                              void* d_out, int out_size) {
    const int*   sent    = (const int*)  d_in[0];
    const int*   length  = (const int*)  d_in[1];
    const float* wordvec = (const float*)d_in[2];
    const float* w_ih0   = (const float*)d_in[3];
    const float* w_hh0   = (const float*)d_in[4];
    const float* b0      = (const float*)d_in[5];
    const float* w_ih1   = (const float*)d_in[6];
    const float* w_hh1   = (const float*)d_in[7];
    const float* b1      = (const float*)d_in[8];
    const float* w_out   = (const float*)d_in[9];
    const float* b_out   = (const float*)d_in[10];
    float* out = (float*)d_out;

    long long tempoff = (long long)out_size - (long long)MROWS * VV;
    if (tempoff < 0) tempoff = 0;
    float* temp = out + tempoff;

    static int smem_set = 0;
    if (!smem_set) {
        cudaFuncSetAttribute(gemm_big,    cudaFuncAttributeMaxDynamicSharedMemorySize, SMEMB);
        cudaFuncSetAttribute(rec_persist, cudaFuncAttributeMaxDynamicSharedMemorySize, SMEMP);
        smem_set = 1;
    }

    float *p_pre0, *p_rowsum;
    fp16 *p_emb, *p_H1, *p_wih0, *p_whh0, *p_w1, *p_wo;
    cudaGetSymbolAddress((void**)&p_pre0, g_pre0);
    cudaGetSymbolAddress((void**)&p_rowsum, g_rowsum);
    cudaGetSymbolAddress((void**)&p_emb,  g_emb);
    cudaGetSymbolAddress((void**)&p_H1,   g_H1);
    cudaGetSymbolAddress((void**)&p_wih0, g_wih0T);
    cudaGetSymbolAddress((void**)&p_whh0, g_whh0T);
    cudaGetSymbolAddress((void**)&p_w1,   g_w1T);
    cudaGetSymbolAddress((void**)&p_wo,   g_woutT);

    zero_state<<<256, 256>>>();
    gather_emb<<<(MROWS * KE + 255) / 256, 256>>>(sent, wordvec);

    dim3 pth(32, 8);
    prep_T<<<dim3(KE / 32, G4 / 32), pth>>>(w_ih0, EE, G4, p_wih0, KE, 0, KE, G4);
    prep_T<<<dim3(HH / 32, G4 / 32), pth>>>(w_hh0, HH, G4, p_whh0, HH, 0, HH, G4);
    prep_T<<<dim3(HH / 32, G4 / 32), pth>>>(w_ih1, HH, G4, p_w1, 2048, 0, HH, G4);
    prep_T<<<dim3(HH / 32, G4 / 32), pth>>>(w_hh1, HH, G4, p_w1, 2048, 1024, HH, G4);
    prep_T<<<dim3(HH / 32, NPADV / 32), pth>>>(w_out, HH, VV, p_wo, HH, 0, HH, NPADV);

    // pre0 = emb @ w_ih0 + b0   [8128,320pad]@[320,4096]
    gemm_big<<<dim3(G4 / 128, 64), 256, SMEMB>>>(
        p_emb, KE, p_wih0, KE, KE, MROWS, G4, b0, p_pre0, G4, nullptr, 0);

    // entire recurrence: one persistent kernel (96 CTAs -> co-residency guaranteed)
    rec_persist<<<NCTA, 512, SMEMP>>>(b1);

    // logits = H1 @ w_out + b_out; fused exp-rowsum
    gemm_big<<<dim3(NPADV / 128, 64), 256, SMEMB>>>(
        p_H1, HH, p_wo, HH, HH, MROWS, VV, b_out, temp, VV, p_rowsum, 2);

    loss_pick<<<(MROWS + 255) / 256, 256>>>(temp, sent);
    if (tempoff > 0) loss_final<<<1, 64>>>(length, out);
}

// round 10
// speedup vs baseline: 1.1778x; 1.1778x over previous
#include <cuda_runtime.h>
#include <cuda_fp16.h>
#include <cstdint>

#define BB   64
#define TT   128
#define VV   10000
#define EE   300
#define HH   1024
#define G4   4096
#define TM1  127
#define MROWS 8128
#define KE   320        // padded E
#define NPADV 10112     // padded V (79*128)

typedef __half fp16;

// ---------------- scratch (device globals) -----------------------------------
__device__ __align__(16) fp16  g_emb [MROWS * KE];
__device__ __align__(16) float g_pre0[(size_t)MROWS * G4];
__device__ __align__(16) float g_gp0 [2 * BB * G4];
__device__ __align__(16) float g_gp1 [4 * BB * G4];
__device__ __align__(16) float g_c0  [BB * HH];
__device__ __align__(16) float g_c1  [BB * HH];
__device__ __align__(16) fp16  g_h0H [BB * HH];
__device__ __align__(16) fp16  g_h1H [BB * HH];
__device__ __align__(16) fp16  g_H1  [(size_t)MROWS * HH];
__device__ __align__(16) fp16  g_wih0T[G4 * KE];
__device__ __align__(16) fp16  g_whh0T[G4 * HH];
__device__ __align__(16) fp16  g_w1T [G4 * 2048];
__device__ __align__(16) fp16  g_woutT[(size_t)NPADV * HH];
__device__ __align__(16) float g_rowsum[MROWS];
__device__ float g_lossb[BB];

// ---------------- fast math (FMA-only exp) -----------------------------------
__device__ __forceinline__ float fexp(float x) {
    x = fminf(x, 88.0f);
    if (x < -87.0f) return 0.0f;
    float t = fmaf(x, 1.4426950408889634f, 12582912.0f);
    float n = t - 12582912.0f;
    int   e = __float_as_int(t) - 0x4B400000;
    float r = fmaf(n, -0.693359375f, x);
    r = fmaf(n, 2.1219444e-4f, r);
    float p = fmaf(8.3333333e-3f, r, 4.1666668e-2f);
    p = fmaf(p, r, 1.6666667e-1f);
    p = fmaf(p, r, 0.5f);
    p = fmaf(p, r, 1.0f);
    p = fmaf(p, r, 1.0f);
    return __int_as_float(__float_as_int(p) + (e << 23));
}
__device__ __forceinline__ float sigf(float x)  { return 1.0f / (1.0f + fexp(-x)); }
__device__ __forceinline__ float tanhf_(float x){ return fmaf(2.0f, sigf(2.0f * x), -1.0f); }

// ---------------- ptx helpers -------------------------------------------------
__device__ __forceinline__ uint32_t smem_u32(const void* p) {
    uint32_t a;
    asm("{ .reg .u64 t; cvta.to.shared.u64 t, %1; cvt.u32.u64 %0, t; }" : "=r"(a) : "l"(p));
    return a;
}
__device__ __forceinline__ void cpa16(uint32_t dst, const void* src, int valid) {
    asm volatile("cp.async.cg.shared.global [%0], [%1], 16, %2;"
                 :: "r"(dst), "l"(src), "r"(valid) : "memory");
}
#define CP_COMMIT()  asm volatile("cp.async.commit_group;" ::: "memory")
#define CP_WAIT(n)   asm volatile("cp.async.wait_group %0;" :: "n"(n) : "memory")

__device__ __forceinline__ void ldm4(uint32_t* r, uint32_t addr) {
    asm volatile("ldmatrix.sync.aligned.m8n8.x4.shared.b16 {%0,%1,%2,%3}, [%4];"
                 : "=r"(r[0]), "=r"(r[1]), "=r"(r[2]), "=r"(r[3]) : "r"(addr));
}
__device__ __forceinline__ void mma16816(float* d, const uint32_t* a, const uint32_t* b) {
    asm volatile(
        "mma.sync.aligned.m16n8k16.row.col.f32.f16.f16.f32 "
        "{%0,%1,%2,%3}, {%4,%5,%6,%7}, {%8,%9}, {%0,%1,%2,%3};"
        : "+f"(d[0]), "+f"(d[1]), "+f"(d[2]), "+f"(d[3])
        : "r"(a[0]), "r"(a[1]), "r"(a[2]), "r"(a[3]), "r"(b[0]), "r"(b[1]));
}
#define SW128(x) ((x) ^ (((x) >> 3) & 0x70))

// ---------------- init / gather / prep ---------------------------------------
__global__ void zero_state() {
    int idx = blockIdx.x * 256 + threadIdx.x;        // 65536 threads
    fp16 z = __float2half_rn(0.0f);
    g_h0H[idx] = z; g_h1H[idx] = z;
    g_c0[idx] = 0.f; g_c1[idx] = 0.f;
    if (idx < MROWS) g_rowsum[idx] = 0.f;
    if (idx < BB) g_lossb[idx] = 0.f;
}

__global__ void gather_emb(const int* __restrict__ sent, const float* __restrict__ wordvec) {
    int idx = blockIdx.x * 256 + threadIdx.x;
    if (idx >= MROWS * KE) return;
    int r = idx / KE, k = idx - r * KE;
    int t = r >> 6, b = r & 63;
    float v = 0.f;
    if (k < EE) { int w = sent[b * TT + t]; v = wordvec[(size_t)w * EE + k]; }
    g_emb[idx] = __float2half_rn(v);
}

__global__ void prep_T(const float* __restrict__ W, int Ksrc, int Nsrc,
                       fp16* __restrict__ O,
                       int Kpad, int koff, int Kspan, int Npad) {
    __shared__ float ts[32][33];
    int k0 = blockIdx.x * 32, n0 = blockIdx.y * 32;
    int tx = threadIdx.x, ty = threadIdx.y;
#pragma unroll
    for (int i = 0; i < 4; i++) {
        int k = k0 + ty + i * 8, n = n0 + tx;
        float v = (k < Ksrc && n < Nsrc) ? W[(size_t)k * Nsrc + n] : 0.f;
        ts[ty + i * 8][tx] = v;
    }
    __syncthreads();
#pragma unroll
    for (int i = 0; i < 4; i++) {
        int n = n0 + ty + i * 8, k = k0 + tx;
        if (n < Npad && k < Kspan)
            O[(size_t)n * Kpad + koff + k] = __float2half_rn(ts[tx][ty + i * 8]);
    }
}

// ---------------- big GEMM (256x128 tile, 3-stage, single-pass fp16) ----------
// Warps 4x2: warp tile 64x64.  mode 0: C = A@B^T + bias.
// mode 2: same + per-row exp-sum into rowsum.
#define BSTAGE 49152    // A 256x128B + B 128x128B
__device__ __forceinline__ void ldstage_b(
    uint32_t st, int tid, int m0, int n0, int k0,
    const fp16* A, int lda, const fp16* B, int ldb, int Mreal)
{
#pragma unroll
    for (int e = tid; e < 2048; e += 256) {          // A: 256 rows x 8 x 16B
        int r = e >> 3, c = e & 7;
        uint32_t sw = SW128((uint32_t)(r * 128 + c * 16));
        int gr = m0 + r;
        int ok = 16;
        if (gr >= Mreal) { ok = 0; gr = 0; }
        cpa16(st + sw, A + (size_t)gr * lda + k0 + c * 8, ok);
    }
#pragma unroll
    for (int e = tid; e < 1024; e += 256) {          // B: 128 rows x 8 x 16B
        int r = e >> 3, c = e & 7;
        uint32_t sw = SW128((uint32_t)(r * 128 + c * 16));
        cpa16(st + 32768 + sw, B + (size_t)(n0 + r) * ldb + k0 + c * 8, 16);
    }
}

__global__ __launch_bounds__(256, 1) void gemm_big(
    const fp16* __restrict__ A, int lda,
    const fp16* __restrict__ B, int ldb,
    int K, int Mreal, int Nreal,
    const float* __restrict__ bias, float* __restrict__ C, int ldc,
    float* __restrict__ rowsum, int mode)
{
    extern __shared__ char smem[];
    int tid = threadIdx.x, lane = tid & 31, wid = tid >> 5;
    int wm = wid & 3, wn = wid >> 2;                 // 4x2 warps
    int n0 = blockIdx.x * 128, m0 = blockIdx.y * 256;
    int nch = K >> 6;

    uint32_t sb = smem_u32(smem);
    float acc[4][8][4];
#pragma unroll
    for (int i = 0; i < 4; i++)
#pragma unroll
        for (int j = 0; j < 8; j++)
#pragma unroll
            for (int v = 0; v < 4; v++) acc[i][j][v] = 0.f;

    ldstage_b(sb, tid, m0, n0, 0, A, lda, B, ldb, Mreal);
    CP_COMMIT();
    if (nch > 1) ldstage_b(sb + BSTAGE, tid, m0, n0, 64, A, lda, B, ldb, Mreal);
    CP_COMMIT();

    for (int ic = 0; ic < nch; ic++) {
        if (ic + 2 < nch)
            ldstage_b(sb + (uint32_t)((ic + 2) % 3) * BSTAGE, tid, m0, n0,
                      (ic + 2) * 64, A, lda, B, ldb, Mreal);
        CP_COMMIT();
        CP_WAIT(2);
        __syncthreads();
        uint32_t st = sb + (uint32_t)(ic % 3) * BSTAGE;
#pragma unroll
        for (int q = 0; q < 4; q++) {
            uint32_t ah[4][4];
            int arow = wm * 64 + (lane & 15);
            int ach  = q * 32 + ((lane >> 4) << 4);
#pragma unroll
            for (int mt = 0; mt < 4; mt++)
                ldm4(ah[mt], st + SW128((uint32_t)((arow + mt * 16) * 128 + ach)));
            uint32_t bh[4][4];
            int brow = wn * 64 + (lane & 7) + (((lane >> 4) & 1) << 3);
            int bch  = q * 32 + (((lane >> 3) & 1) << 4);
#pragma unroll
            for (int p = 0; p < 4; p++)
                ldm4(bh[p], st + 32768 + SW128((uint32_t)((brow + p * 16) * 128 + bch)));
#pragma unroll
            for (int mt = 0; mt < 4; mt++)
#pragma unroll
                for (int p = 0; p < 4; p++)
#pragma unroll
                    for (int h = 0; h < 2; h++)
                        mma16816(acc[mt][p * 2 + h], ah[mt], &bh[p][h * 2]);
        }
        __syncthreads();
    }

    int rbase = m0 + wm * 64 + (lane >> 2);
    int cbase = n0 + wn * 64 + (lane & 3) * 2;
    float rs[8];
#pragma unroll
    for (int i = 0; i < 8; i++) rs[i] = 0.f;
#pragma unroll
    for (int mt = 0; mt < 4; mt++)
#pragma unroll
        for (int nt = 0; nt < 8; nt++) {
            int col = cbase + nt * 8;
            int r0 = rbase + mt * 16;
            if (col < Nreal) {
                float ba = bias[col], bb = bias[col + 1];
#pragma unroll
                for (int rp = 0; rp < 2; rp++) {
                    int row = r0 + rp * 8;
                    if (row < Mreal) {
                        float v0 = acc[mt][nt][rp * 2]     + ba;
                        float v1 = acc[mt][nt][rp * 2 + 1] + bb;
                        C[(size_t)row * ldc + col]     = v0;
                        C[(size_t)row * ldc + col + 1] = v1;
                        if (mode == 2) {
                            float s = fexp(v0);
                            if (col + 1 < Nreal) s += fexp(v1);
                            rs[mt * 2 + rp] += s;
                        }
                    }
                }
            }
        }
    if (mode == 2) {
#pragma unroll
        for (int i = 0; i < 8; i++) {
            rs[i] += __shfl_xor_sync(0xffffffffu, rs[i], 1);
            rs[i] += __shfl_xor_sync(0xffffffffu, rs[i], 2);
        }
        if ((lane & 3) == 0) {
#pragma unroll
            for (int mt = 0; mt < 4; mt++)
#pragma unroll
                for (int rp = 0; rp < 2; rp++) {
                    int row = rbase + mt * 16 + rp * 8;
                    if (row < Mreal) atomicAdd(&rowsum[row], rs[mt * 2 + rp]);
                }
        }
    }
}

// ---------------- wavefront recurrence GEMM (64x128, single-pass, 3-stage) ----
// grid (32, 1, 6-zoff): z+zoff in {0,1}: layer0 K-slice z*512 of h0@whh0 -> gp0[z]
//                       z+zoff in {2..5}: layer1 K-slice zz*512 of [h0|h1]@w1 -> gp1[zz]
#define RSTAGE 24576
__device__ __forceinline__ void ldstage_r(
    uint32_t st, int tid, int n0, int kA, int kB,
    const fp16* Ah, const fp16* B, int ldb)
{
#pragma unroll
    for (int e = tid; e < 512; e += 256) {
        int r = e >> 3, c = e & 7;
        uint32_t sw = SW128((uint32_t)(r * 128 + c * 16));
        cpa16(st + sw, Ah + (size_t)r * 1024 + kA + c * 8, 16);
    }
#pragma unroll
    for (int e = tid; e < 1024; e += 256) {
        int r = e >> 3, c = e & 7;
        uint32_t sw = SW128((uint32_t)(r * 128 + c * 16));
        cpa16(st + 8192 + sw, B + (size_t)(n0 + r) * ldb + kB + c * 8, 16);
    }
}

__global__ __launch_bounds__(256, 2) void rgemm(int zoff) {
    extern __shared__ char smem[];
    int tid = threadIdx.x, lane = tid & 31, wn = tid >> 5;
    int n0 = blockIdx.x * 128;
    int z = blockIdx.z + zoff;

    const fp16 *Ah, *Bp;
    float* gpo;
    int kA, kB, ldb, zi;
    if (z < 2) {
        Ah = g_h0H; kA = z * 512;
        Bp = g_whh0T; ldb = 1024; kB = z * 512;
        gpo = g_gp0; zi = z;
    } else {
        int zz = z - 2;
        if (zz < 2) { Ah = g_h0H; kA = zz * 512; }
        else        { Ah = g_h1H; kA = (zz - 2) * 512; }
        Bp = g_w1T; ldb = 2048; kB = zz * 512;
        gpo = g_gp1; zi = zz;
    }

    uint32_t sb = smem_u32(smem);
    float acc[4][2][4];
#pragma unroll
    for (int i = 0; i < 4; i++)
#pragma unroll
        for (int j = 0; j < 2; j++)
#pragma unroll
            for (int v = 0; v < 4; v++) acc[i][j][v] = 0.f;

    ldstage_r(sb, tid, n0, kA, kB, Ah, Bp, ldb);
    CP_COMMIT();
    ldstage_r(sb + RSTAGE, tid, n0, kA + 64, kB + 64, Ah, Bp, ldb);
    CP_COMMIT();

    for (int ic = 0; ic < 8; ic++) {
        if (ic + 2 < 8)
            ldstage_r(sb + (uint32_t)((ic + 2) % 3) * RSTAGE, tid, n0,
                      kA + (ic + 2) * 64, kB + (ic + 2) * 64, Ah, Bp, ldb);
        CP_COMMIT();
        CP_WAIT(2);
        __syncthreads();
        uint32_t st = sb + (uint32_t)(ic % 3) * RSTAGE;
#pragma unroll
        for (int q = 0; q < 4; q++) {
            uint32_t ah[4][4];
            int arow = lane & 15;
            int ach  = q * 32 + ((lane >> 4) << 4);
#pragma unroll
            for (int mt = 0; mt < 4; mt++)
                ldm4(ah[mt], st + SW128((uint32_t)((arow + mt * 16) * 128 + ach)));
            uint32_t bh[4];
            int brow = wn * 16 + (lane & 7) + (((lane >> 4) & 1) << 3);
            int bch  = q * 32 + (((lane >> 3) & 1) << 4);
            ldm4(bh, st + 8192 + SW128((uint32_t)(brow * 128 + bch)));
#pragma unroll
            for (int mt = 0; mt < 4; mt++)
#pragma unroll
                for (int h = 0; h < 2; h++)
                    mma16816(acc[mt][h], ah[mt], &bh[h * 2]);
        }
        __syncthreads();
    }

    int rbase = zi * 64 + (lane >> 2);
    int cbase = n0 + wn * 16 + (lane & 3) * 2;
#pragma unroll
    for (int mt = 0; mt < 4; mt++)
#pragma unroll
        for (int nt = 0; nt < 2; nt++) {
            int col = cbase + nt * 8;
            int r0 = rbase + mt * 16;
            gpo[(size_t)r0 * G4 + col]           = acc[mt][nt][0];
            gpo[(size_t)r0 * G4 + col + 1]       = acc[mt][nt][1];
            gpo[(size_t)(r0 + 8) * G4 + col]     = acc[mt][nt][2];
            gpo[(size_t)(r0 + 8) * G4 + col + 1] = acc[mt][nt][3];
        }
}

// ---------------- combined LSTM update: upd0(t+1) || upd1(t) ------------------
// nz0: #gp0 partials for upd0 (0 = prologue, -1 = skip upd0); do1: run upd1(t)
__global__ __launch_bounds__(256) void upd_both(int t, int nz0, int do1,
                                                const float* __restrict__ b1) {
    int gidx = blockIdx.x * 256 + threadIdx.x;   // 131072
    if (gidx < 65536) {
        if (nz0 < 0) return;
        int b = gidx >> 10, h = gidx & 1023;
        const float* pre = g_pre0 + ((size_t)((t + 1) * 64 + b)) * G4;
        float gi = pre[h], gf = pre[1024 + h], gg = pre[2048 + h], go = pre[3072 + h];
        for (int z = 0; z < nz0; z++) {
            const float* gpp = g_gp0 + ((size_t)(z * 64 + b)) * G4;
            gi += gpp[h]; gf += gpp[1024 + h]; gg += gpp[2048 + h]; go += gpp[3072 + h];
        }
        float c = sigf(gf) * g_c0[gidx] + sigf(gi) * tanhf_(gg);
        float hn = sigf(go) * tanhf_(c);
        g_c0[gidx] = c;
        g_h0H[gidx] = __float2half_rn(hn);
    } else {
        if (!do1) return;
        int idx = gidx - 65536;
        int b = idx >> 10, h = idx & 1023;
        float gi = b1[h], gf = b1[1024 + h], gg = b1[2048 + h], go = b1[3072 + h];
#pragma unroll
        for (int z = 0; z < 4; z++) {
            const float* gpp = g_gp1 + ((size_t)(z * 64 + b)) * G4;
            gi += gpp[h]; gf += gpp[1024 + h]; gg += gpp[2048 + h]; go += gpp[3072 + h];
        }
        float c = sigf(gf) * g_c1[idx] + sigf(gi) * tanhf_(gg);
        float hn = sigf(go) * tanhf_(c);
        g_c1[idx] = c;
        fp16 hi = __float2half_rn(hn);
        g_h1H[idx] = hi;
        g_H1[((size_t)b * TM1 + t) * HH + h] = hi;
    }
}

// ---------------- loss --------------------------------------------------------
__global__ void loss_pick(const float* __restrict__ temp, const int* __restrict__ sent) {
    int idx = blockIdx.x * 256 + threadIdx.x;
    if (idx >= MROWS) return;
    int b = idx / TM1, t = idx - b * TM1;
    int gt = sent[b * TT + t + 1];
    if (gt != 0) {
        float lp = temp[(size_t)idx * VV + gt] - logf(g_rowsum[idx]);
        atomicAdd(&g_lossb[b], lp);
    }
}

__global__ void loss_final(const int* __restrict__ length, float* __restrict__ out) {
    int tid = threadIdx.x;  // 64 threads
    float v = -g_lossb[tid] / (float)length[tid];
#pragma unroll
    for (int o = 16; o; o >>= 1) v += __shfl_xor_sync(0xffffffffu, v, o);
    __shared__ float r2[2];
    if ((tid & 31) == 0) r2[tid >> 5] = v;
    __syncthreads();
    if (tid == 0) out[0] = r2[0] + r2[1];
}

// ---------------- launch ------------------------------------------------------
#define SMEMB 147456   // gemm_big: 3 * 49152
#define SMEMR 73728    // rgemm:    3 * 24576

extern "C" void kernel_launch(void* const* d_in, const int* in_sizes, int n_in,
                              void* d_out, int out_size) {
    const int*   sent    = (const int*)  d_in[0];
    const int*   length  = (const int*)  d_in[1];
    const float* wordvec = (const float*)d_in[2];
    const float* w_ih0   = (const float*)d_in[3];
    const float* w_hh0   = (const float*)d_in[4];
    const float* b0      = (const float*)d_in[5];
    const float* w_ih1   = (const float*)d_in[6];
    const float* w_hh1   = (const float*)d_in[7];
    const float* b1      = (const float*)d_in[8];
    const float* w_out   = (const float*)d_in[9];
    const float* b_out   = (const float*)d_in[10];
    float* out = (float*)d_out;

    long long tempoff = (long long)out_size - (long long)MROWS * VV;
    if (tempoff < 0) tempoff = 0;
    float* temp = out + tempoff;

    static int smem_set = 0;
    if (!smem_set) {
        cudaFuncSetAttribute(gemm_big, cudaFuncAttributeMaxDynamicSharedMemorySize, SMEMB);
        cudaFuncSetAttribute(rgemm,    cudaFuncAttributeMaxDynamicSharedMemorySize, SMEMR);
        smem_set = 1;
    }

    float *p_pre0, *p_rowsum;
    fp16 *p_emb, *p_H1, *p_wih0, *p_whh0, *p_w1, *p_wo;
    cudaGetSymbolAddress((void**)&p_pre0, g_pre0);
    cudaGetSymbolAddress((void**)&p_rowsum, g_rowsum);
    cudaGetSymbolAddress((void**)&p_emb,  g_emb);
    cudaGetSymbolAddress((void**)&p_H1,   g_H1);
    cudaGetSymbolAddress((void**)&p_wih0, g_wih0T);
    cudaGetSymbolAddress((void**)&p_whh0, g_whh0T);
    cudaGetSymbolAddress((void**)&p_w1,   g_w1T);
    cudaGetSymbolAddress((void**)&p_wo,   g_woutT);

    zero_state<<<256, 256>>>();
    gather_emb<<<(MROWS * KE + 255) / 256, 256>>>(sent, wordvec);

    dim3 pth(32, 8);
    prep_T<<<dim3(KE / 32, G4 / 32), pth>>>(w_ih0, EE, G4, p_wih0, KE, 0, KE, G4);
    prep_T<<<dim3(HH / 32, G4 / 32), pth>>>(w_hh0, HH, G4, p_whh0, HH, 0, HH, G4);
    prep_T<<<dim3(HH / 32, G4 / 32), pth>>>(w_ih1, HH, G4, p_w1, 2048, 0, HH, G4);
    prep_T<<<dim3(HH / 32, G4 / 32), pth>>>(w_hh1, HH, G4, p_w1, 2048, 1024, HH, G4);
    prep_T<<<dim3(HH / 32, NPADV / 32), pth>>>(w_out, HH, VV, p_wo, HH, 0, HH, NPADV);

    // pre0 = emb @ w_ih0 + b0   [8128,320pad]@[320,4096]   (M-tiles of 256)
    gemm_big<<<dim3(G4 / 128, 32), 256, SMEMB>>>(
        p_emb, KE, p_wih0, KE, KE, MROWS, G4, b0, p_pre0, G4, nullptr, 0);

    // prologue: h0(0) from pre0[0] only
    upd_both<<<512, 256>>>(-1, 0, 0, b1);

    // wavefront: gemm0(s+1) || gemm1(s), then upd0(s+1) || upd1(s)
    for (int s = 0; s < TM1 - 1; s++) {
        rgemm<<<dim3(32, 1, 6), 256, SMEMR>>>(0);
        upd_both<<<512, 256>>>(s, 2, 1, b1);
    }
    // epilogue: gemm1(126) + upd1(126)
    rgemm<<<dim3(32, 1, 4), 256, SMEMR>>>(2);
    upd_both<<<512, 256>>>(TM1 - 1, -1, 1, b1);

    // logits = H1 @ w_out + b_out; fused exp-rowsum  (M-tiles of 256)
    gemm_big<<<dim3(NPADV / 128, 32), 256, SMEMB>>>(
        p_H1, HH, p_wo, HH, HH, MROWS, VV, b_out, temp, VV, p_rowsum, 2);

    loss_pick<<<(MROWS + 255) / 256, 256>>>(temp, sent);
    if (tempoff > 0) loss_final<<<1, 64>>>(length, out);
}